// round 8
// baseline (speedup 1.0000x reference)
#include <cuda_runtime.h>
#include <math.h>

#define B   32
#define T   128
#define S   128
#define DIN 1024
#define H   1024
#define C   1024
#define G4  4096   // 4*H

// ---------------- scratch (device globals; no allocations allowed) ----------------
__device__ __align__(16) float g_h[H * B];        // h, feature-major [h][b]
__device__ __align__(16) float g_c[H * B];        // c, feature-major
__device__ __align__(16) float g_attn[H * B];     // attention output (input feeding), feature-major
__device__ __align__(16) float g_gp[3][G4 * B];   // gate GEMM partials (x / attn / h segments)
__device__ __align__(16) float g_op[4][H * B];    // output GEMM partials (4 K-segments)
__device__ __align__(16) float g_ctx[C * B];      // attended context, feature-major
__device__ __align__(16) float4 g_sp4[B * S];     // score partials, 4 H-slices per (b,s)
__device__ __align__(16) float g_xT[T * DIN * B]; // x transposed: [t][k][b]   (16 MB)
__device__ __align__(16) float g_P[B * S * H];    // context @ Wq : [b*S+s][h]  (16 MB)

__device__ __forceinline__ float sigf(float x) { return 1.f / (1.f + expf(-x)); }

// ---------------- packed f32x2 helpers (sm_103a FFMA2: 2 fp32 FMA/inst, bit-exact) -------
__device__ __forceinline__ unsigned long long pk2(float lo, float hi) {
    unsigned long long r;
    asm("mov.b64 %0, {%1, %2};" : "=l"(r) : "f"(lo), "f"(hi));
    return r;
}
__device__ __forceinline__ unsigned long long ffma2(unsigned long long a, unsigned long long b,
                                                    unsigned long long c) {
    unsigned long long d;
    asm("fma.rn.f32x2 %0, %1, %2, %3;" : "=l"(d) : "l"(a), "l"(b), "l"(c));
    return d;
}
__device__ __forceinline__ float hadd2(unsigned long long v) {
    float lo, hi;
    asm("mov.b64 {%0, %1}, %2;" : "=f"(lo), "=f"(hi) : "l"(v));
    return lo + hi;
}
__device__ __forceinline__ float2 unpk2(unsigned long long v) {
    float lo, hi;
    asm("mov.b64 {%0, %1}, %2;" : "=f"(lo), "=f"(hi) : "l"(v));
    return make_float2(lo, hi);
}

// ---------------- init: reset recurrent state every launch (determinism) ----------------
__global__ void init_state() {
    int i = blockIdx.x * blockDim.x + threadIdx.x;
    if (i < H * B) { g_h[i] = 0.f; g_c[i] = 0.f; g_attn[i] = 0.f; }
}

// ---------------- transpose x[B,T,Din] -> g_xT[t][k][b] ----------------
__global__ void transpose_x(const float* __restrict__ x) {
    __shared__ float sm[32][33];
    int t  = blockIdx.x;
    int k0 = blockIdx.y * 32;
    int tx = threadIdx.x, ty = threadIdx.y;   // (32, 8)
#pragma unroll
    for (int i = 0; i < 4; i++) {
        int b = ty + i * 8;
        sm[b][tx] = x[(b * T + t) * DIN + k0 + tx];   // coalesced over k
    }
    __syncthreads();
#pragma unroll
    for (int i = 0; i < 4; i++) {
        int k = ty + i * 8;
        g_xT[(t * DIN + k0 + k) * B + tx] = sm[tx][k]; // coalesced over b
    }
}

// ---------------- P = context @ Wq, tiled GEMM: M=B*S=4096, N=H, K=C ----------------
__global__ void __launch_bounds__(256) compute_P_tiled(const float* __restrict__ context,
                                                       const float* __restrict__ Wq) {
    __shared__ float sA[16][68];   // [k][m], padded
    __shared__ float sB[16][64];   // [k][n]
    int tid = threadIdx.x;
    int rm0 = blockIdx.x * 64;     // row tile (b*S+s)
    int cn0 = blockIdx.y * 64;     // h tile
    int ty = tid >> 4, tx = tid & 15;
    int m0 = ty * 4, n0 = tx * 4;

    unsigned long long acc[4][2];
#pragma unroll
    for (int i = 0; i < 4; i++) { acc[i][0] = 0ull; acc[i][1] = 0ull; }

    int lam = tid >> 2;            // 0..63 (m)
    int lak = (tid & 3) * 4;       // 0,4,8,12
    int lbk = tid >> 4;            // 0..15
    int lbn = (tid & 15) * 4;      // n

    for (int c0 = 0; c0 < C; c0 += 16) {
        float4 av = *(const float4*)(context + (rm0 + lam) * C + c0 + lak);
        sA[lak + 0][lam] = av.x; sA[lak + 1][lam] = av.y;
        sA[lak + 2][lam] = av.z; sA[lak + 3][lam] = av.w;
        *(float4*)(&sB[lbk][lbn]) = *(const float4*)(Wq + (c0 + lbk) * H + cn0 + lbn);
        __syncthreads();
#pragma unroll
        for (int k = 0; k < 16; k++) {
            float4 a4 = *(const float4*)(&sA[k][m0]);
            float4 b4 = *(const float4*)(&sB[k][n0]);
            unsigned long long b01 = pk2(b4.x, b4.y), b23 = pk2(b4.z, b4.w);
            float am[4] = {a4.x, a4.y, a4.z, a4.w};
#pragma unroll
            for (int i = 0; i < 4; i++) {
                unsigned long long a2 = pk2(am[i], am[i]);
                acc[i][0] = ffma2(a2, b01, acc[i][0]);
                acc[i][1] = ffma2(a2, b23, acc[i][1]);
            }
        }
        __syncthreads();
    }
#pragma unroll
    for (int i = 0; i < 4; i++) {
        float2 lo = unpk2(acc[i][0]), hi = unpk2(acc[i][1]);
        *(float4*)(g_P + (rm0 + m0 + i) * H + cn0 + n0) = make_float4(lo.x, lo.y, hi.x, hi.y);
    }
}

// ---------------- gates partial GEMMs: 3 K=1024 segments, 4 rows x 4 cols per thread ----
// k-packed FFMA2: weight pairs come free from float4 register pairs; 8 LDG per 32 FFMA2.
__global__ void __launch_bounds__(32) gates_part(const float* __restrict__ W_ih,
                                                 const float* __restrict__ W_hh, int t) {
    int seg = blockIdx.y;
    int tid = blockIdx.x * 32 + threadIdx.x;   // 0..8191
    int r0  = (tid >> 3) * 4;                  // rows r0..r0+3
    int bq  = (tid & 7) * 4;                   // batch cols bq..bq+3

    const float* w;
    const float* act;
    int ws;
    if (seg == 0)      { w = W_ih + r0 * 2048;        act = g_xT + t * DIN * B; ws = 2048; }
    else if (seg == 1) { w = W_ih + r0 * 2048 + 1024; act = g_attn;             ws = 2048; }
    else               { w = W_hh + r0 * 1024;        act = g_h;                ws = 1024; }

    unsigned long long acc[4][4];
#pragma unroll
    for (int i = 0; i < 4; i++)
#pragma unroll
        for (int c = 0; c < 4; c++) acc[i][c] = 0ull;

#pragma unroll 2
    for (int k = 0; k < 1024; k += 4) {
        float4 wv0 = *(const float4*)(w + k);
        float4 wv1 = *(const float4*)(w + ws + k);
        float4 wv2 = *(const float4*)(w + 2 * ws + k);
        float4 wv3 = *(const float4*)(w + 3 * ws + k);
        float4 a0 = *(const float4*)(act + (k + 0) * B + bq);
        float4 a1 = *(const float4*)(act + (k + 1) * B + bq);
        float4 a2 = *(const float4*)(act + (k + 2) * B + bq);
        float4 a3 = *(const float4*)(act + (k + 3) * B + bq);
        {   // k-pair (k, k+1)
            unsigned long long px = pk2(a0.x, a1.x), py = pk2(a0.y, a1.y);
            unsigned long long pz = pk2(a0.z, a1.z), pw = pk2(a0.w, a1.w);
            unsigned long long q0 = pk2(wv0.x, wv0.y), q1 = pk2(wv1.x, wv1.y);
            unsigned long long q2 = pk2(wv2.x, wv2.y), q3 = pk2(wv3.x, wv3.y);
            acc[0][0] = ffma2(q0, px, acc[0][0]); acc[0][1] = ffma2(q0, py, acc[0][1]);
            acc[0][2] = ffma2(q0, pz, acc[0][2]); acc[0][3] = ffma2(q0, pw, acc[0][3]);
            acc[1][0] = ffma2(q1, px, acc[1][0]); acc[1][1] = ffma2(q1, py, acc[1][1]);
            acc[1][2] = ffma2(q1, pz, acc[1][2]); acc[1][3] = ffma2(q1, pw, acc[1][3]);
            acc[2][0] = ffma2(q2, px, acc[2][0]); acc[2][1] = ffma2(q2, py, acc[2][1]);
            acc[2][2] = ffma2(q2, pz, acc[2][2]); acc[2][3] = ffma2(q2, pw, acc[2][3]);
            acc[3][0] = ffma2(q3, px, acc[3][0]); acc[3][1] = ffma2(q3, py, acc[3][1]);
            acc[3][2] = ffma2(q3, pz, acc[3][2]); acc[3][3] = ffma2(q3, pw, acc[3][3]);
        }
        {   // k-pair (k+2, k+3)
            unsigned long long px = pk2(a2.x, a3.x), py = pk2(a2.y, a3.y);
            unsigned long long pz = pk2(a2.z, a3.z), pw = pk2(a2.w, a3.w);
            unsigned long long q0 = pk2(wv0.z, wv0.w), q1 = pk2(wv1.z, wv1.w);
            unsigned long long q2 = pk2(wv2.z, wv2.w), q3 = pk2(wv3.z, wv3.w);
            acc[0][0] = ffma2(q0, px, acc[0][0]); acc[0][1] = ffma2(q0, py, acc[0][1]);
            acc[0][2] = ffma2(q0, pz, acc[0][2]); acc[0][3] = ffma2(q0, pw, acc[0][3]);
            acc[1][0] = ffma2(q1, px, acc[1][0]); acc[1][1] = ffma2(q1, py, acc[1][1]);
            acc[1][2] = ffma2(q1, pz, acc[1][2]); acc[1][3] = ffma2(q1, pw, acc[1][3]);
            acc[2][0] = ffma2(q2, px, acc[2][0]); acc[2][1] = ffma2(q2, py, acc[2][1]);
            acc[2][2] = ffma2(q2, pz, acc[2][2]); acc[2][3] = ffma2(q2, pw, acc[2][3]);
            acc[3][0] = ffma2(q3, px, acc[3][0]); acc[3][1] = ffma2(q3, py, acc[3][1]);
            acc[3][2] = ffma2(q3, pz, acc[3][2]); acc[3][3] = ffma2(q3, pw, acc[3][3]);
        }
    }

#pragma unroll
    for (int i = 0; i < 4; i++) {
        float4 o = make_float4(hadd2(acc[i][0]), hadd2(acc[i][1]),
                               hadd2(acc[i][2]), hadd2(acc[i][3]));
        *(float4*)(&g_gp[seg][(r0 + i) * B + bq]) = o;
    }
}

// ---------------- cell + partial scores: grid (B, 4), 256 threads ----------------
// Block (b,q) owns features [q*256, q*256+256): computes the LSTM cell for its slice
// (summing 3 gate partials + biases), keeps h-slice in smem, then emits partial scores
// sp[b][s][q] = sum_{j in slice} h_j * P[b,s,j] for all s.
__global__ void __launch_bounds__(256) cell_scores(const float* __restrict__ b_ih,
                                                   const float* __restrict__ b_hh) {
    __shared__ float sh[256];
    int b   = blockIdx.x;
    int q   = blockIdx.y;
    int tid = threadIdx.x;
    int j   = q * 256 + tid;

    // ---- cell update for feature j, batch b ----
    {
        int i0 = j * B + b, i1 = (H + j) * B + b, i2 = (2 * H + j) * B + b, i3 = (3 * H + j) * B + b;
        float ig = g_gp[0][i0] + g_gp[1][i0] + g_gp[2][i0] + b_ih[j]         + b_hh[j];
        float fg = g_gp[0][i1] + g_gp[1][i1] + g_gp[2][i1] + b_ih[H + j]     + b_hh[H + j];
        float gg = g_gp[0][i2] + g_gp[1][i2] + g_gp[2][i2] + b_ih[2 * H + j] + b_hh[2 * H + j];
        float og = g_gp[0][i3] + g_gp[1][i3] + g_gp[2][i3] + b_ih[3 * H + j] + b_hh[3 * H + j];

        float c  = g_c[j * B + b];
        float cn = sigf(fg) * c + sigf(ig) * tanhf(gg);
        float hn = sigf(og) * tanhf(cn);
        g_c[j * B + b] = cn;
        g_h[j * B + b] = hn;
        sh[tid] = hn;
    }
    __syncthreads();

    // ---- partial scores: each warp handles 16 of the S=128 scores ----
    int wrp  = tid >> 5;
    int lane = tid & 31;
    float4 h0 = *(const float4*)(sh + lane * 8);
    float4 h1 = *(const float4*)(sh + lane * 8 + 4);

    for (int s = wrp; s < S; s += 8) {
        const float* p = g_P + (b * S + s) * H + q * 256 + lane * 8;
        float4 p0 = *(const float4*)(p);
        float4 p1 = *(const float4*)(p + 4);
        float acc = p0.x * h0.x + p0.y * h0.y + p0.z * h0.z + p0.w * h0.w
                  + p1.x * h1.x + p1.y * h1.y + p1.z * h1.z + p1.w * h1.w;
#pragma unroll
        for (int o = 16; o > 0; o >>= 1) acc += __shfl_xor_sync(0xffffffffu, acc, o);
        if (lane == 0) ((float*)&g_sp4[b * S + s])[q] = acc;
    }
}

// ---------------- softmax + ctx: grid (B, 4), 256 threads ----------------
// Each block redoes the tiny softmax (sum of 4 partials per score, identical across
// the 4 c-blocks -> deterministic) and accumulates its 256 context channels.
__global__ void __launch_bounds__(256) softmax_ctx2(const float* __restrict__ context) {
    __shared__ float sal[128];
    __shared__ float sred[128];
    int b   = blockIdx.x;
    int cq  = blockIdx.y;
    int tid = threadIdx.x;

    float sc = 0.f;
    if (tid < 128) {
        float4 sp = g_sp4[b * S + tid];
        sc = (sp.x + sp.y) + (sp.z + sp.w);
        sred[tid] = sc;
    }
    __syncthreads();
#pragma unroll
    for (int o = 64; o > 0; o >>= 1) {
        if (tid < o) sred[tid] = fmaxf(sred[tid], sred[tid + o]);
        __syncthreads();
    }
    float mx = sred[0];
    __syncthreads();
    float e = 0.f;
    if (tid < 128) { e = expf(sc - mx); sred[tid] = e; }
    __syncthreads();
#pragma unroll
    for (int o = 64; o > 0; o >>= 1) {
        if (tid < o) sred[tid] += sred[tid + o];
        __syncthreads();
    }
    float inv = 1.f / sred[0];
    __syncthreads();
    if (tid < 128) sal[tid] = e * inv;   // normalized alpha
    __syncthreads();

    // ---- ctx: one channel per thread ----
    int c = cq * 256 + tid;
    const float* cb = context + b * S * C + c;
    float acc = 0.f;
#pragma unroll 8
    for (int s = 0; s < S; s++) acc += sal[s] * cb[s * C];
    g_ctx[c * B + b] = acc;
}

// ---------------- output projection partials: 4 K=512 segments, 2 rows x 4 cols ----------------
// seg 0: Wout[:,0:512]@ctx[0:512]   seg 1: Wout[:,512:1024]@ctx[512:]
// seg 2: Wout[:,1024:1536]@h[0:512] seg 3: Wout[:,1536:2048]@h[512:]
__global__ void __launch_bounds__(32) out_part(const float* __restrict__ Wout) {
    int seg = blockIdx.y;                      // 0..3
    int tid = blockIdx.x * 32 + threadIdx.x;   // 0..4095
    int r0  = (tid >> 3) * 2;                  // rows r0, r0+1
    int bq  = (tid & 7) * 4;
    const float* w   = Wout + r0 * 2048 + seg * 512;
    const float* act = (seg < 2 ? g_ctx : g_h) + (seg & 1) * 512 * B;

    unsigned long long acc[2][4];
#pragma unroll
    for (int i = 0; i < 2; i++)
#pragma unroll
        for (int c = 0; c < 4; c++) acc[i][c] = 0ull;

#pragma unroll 2
    for (int k = 0; k < 512; k += 4) {
        float4 wv0 = *(const float4*)(w + k);
        float4 wv1 = *(const float4*)(w + 2048 + k);
        float4 a0 = *(const float4*)(act + (k + 0) * B + bq);
        float4 a1 = *(const float4*)(act + (k + 1) * B + bq);
        float4 a2 = *(const float4*)(act + (k + 2) * B + bq);
        float4 a3 = *(const float4*)(act + (k + 3) * B + bq);
        {
            unsigned long long px = pk2(a0.x, a1.x), py = pk2(a0.y, a1.y);
            unsigned long long pz = pk2(a0.z, a1.z), pw = pk2(a0.w, a1.w);
            unsigned long long q0 = pk2(wv0.x, wv0.y), q1 = pk2(wv1.x, wv1.y);
            acc[0][0] = ffma2(q0, px, acc[0][0]); acc[0][1] = ffma2(q0, py, acc[0][1]);
            acc[0][2] = ffma2(q0, pz, acc[0][2]); acc[0][3] = ffma2(q0, pw, acc[0][3]);
            acc[1][0] = ffma2(q1, px, acc[1][0]); acc[1][1] = ffma2(q1, py, acc[1][1]);
            acc[1][2] = ffma2(q1, pz, acc[1][2]); acc[1][3] = ffma2(q1, pw, acc[1][3]);
        }
        {
            unsigned long long px = pk2(a2.x, a3.x), py = pk2(a2.y, a3.y);
            unsigned long long pz = pk2(a2.z, a3.z), pw = pk2(a2.w, a3.w);
            unsigned long long q0 = pk2(wv0.z, wv0.w), q1 = pk2(wv1.z, wv1.w);
            acc[0][0] = ffma2(q0, px, acc[0][0]); acc[0][1] = ffma2(q0, py, acc[0][1]);
            acc[0][2] = ffma2(q0, pz, acc[0][2]); acc[0][3] = ffma2(q0, pw, acc[0][3]);
            acc[1][0] = ffma2(q1, px, acc[1][0]); acc[1][1] = ffma2(q1, py, acc[1][1]);
            acc[1][2] = ffma2(q1, pz, acc[1][2]); acc[1][3] = ffma2(q1, pw, acc[1][3]);
        }
    }

#pragma unroll
    for (int i = 0; i < 2; i++) {
        float4 o = make_float4(hadd2(acc[i][0]), hadd2(acc[i][1]),
                               hadd2(acc[i][2]), hadd2(acc[i][3]));
        *(float4*)(&g_op[seg][(r0 + i) * B + bq]) = o;
    }
}

// ---------------- combine output partials, tanh, write attn state + final output ----------------
__global__ void __launch_bounds__(256) out_combine(const float* __restrict__ b_out,
                                                   float* __restrict__ out, int t) {
    int tid = blockIdx.x * blockDim.x + threadIdx.x;   // 32768
    int b = tid & 31, r = tid >> 5;
    int idx = r * B + b;
    float v = tanhf(g_op[0][idx] + g_op[1][idx] + g_op[2][idx] + g_op[3][idx] + b_out[r]);
    g_attn[idx] = v;
    out[b * (T * H) + t * H + r] = v;
}

// ---------------- launch ----------------
extern "C" void kernel_launch(void* const* d_in, const int* in_sizes, int n_in,
                              void* d_out, int out_size) {
    const float* x       = (const float*)d_in[0];
    const float* context = (const float*)d_in[1];
    const float* W_ih    = (const float*)d_in[2];
    const float* W_hh    = (const float*)d_in[3];
    const float* b_ih    = (const float*)d_in[4];
    const float* b_hh    = (const float*)d_in[5];
    const float* Wq      = (const float*)d_in[6];
    const float* Wout    = (const float*)d_in[7];
    const float* b_out   = (const float*)d_in[8];
    float* out = (float*)d_out;

    init_state<<<(H * B) / 256, 256>>>();
    transpose_x<<<dim3(T, DIN / 32), dim3(32, 8)>>>(x);
    compute_P_tiled<<<dim3(64, 16), 256>>>(context, Wq);

    for (int t = 0; t < T; t++) {
        gates_part<<<dim3(256, 3), 32>>>(W_ih, W_hh, t);
        cell_scores<<<dim3(B, 4), 256>>>(b_ih, b_hh);
        softmax_ctx2<<<dim3(B, 4), 256>>>(context);
        out_part<<<dim3(128, 4), 32>>>(Wout);
        out_combine<<<128, 256>>>(b_out, out, t);
    }
}

// round 15
// speedup vs baseline: 1.8295x; 1.8295x over previous
#include <cuda_runtime.h>
#include <math.h>

#define B   32
#define T   128
#define S   128
#define DIN 1024
#define H   1024
#define C   1024
#define G4  4096   // 4*H
#define NGP 12     // gate partials: 3 segments x 4 K-chunks
#define NOP 8      // output partials: 8 K-chunks of 256

// ---------------- scratch (device globals; no allocations allowed) ----------------
__device__ __align__(16) float g_h[H * B];        // h, feature-major [h][b]
__device__ __align__(16) float g_c[H * B];        // c, feature-major
__device__ __align__(16) float g_attn[H * B];     // attention output (input feeding), feature-major
__device__ __align__(16) float g_gp[NGP][G4 * B]; // gate GEMM partials
__device__ __align__(16) float g_op[NOP][H * B];  // output GEMM partials
__device__ __align__(16) float g_ctx[C * B];      // attended context, feature-major
__device__ __align__(16) float4 g_sp4[B * S];     // score partials, 4 H-slices per (b,s)
__device__ __align__(16) float g_xT[T * DIN * B]; // x transposed: [t][k][b]   (16 MB)
__device__ __align__(16) float g_P[B * S * H];    // context @ Wq : [b*S+s][h]  (16 MB)

__device__ __forceinline__ float sigf(float x) { return 1.f / (1.f + expf(-x)); }

// ---------------- packed f32x2 helpers (sm_103a FFMA2: 2 fp32 FMA/inst, bit-exact) -------
__device__ __forceinline__ unsigned long long pk2(float lo, float hi) {
    unsigned long long r;
    asm("mov.b64 %0, {%1, %2};" : "=l"(r) : "f"(lo), "f"(hi));
    return r;
}
__device__ __forceinline__ unsigned long long ffma2(unsigned long long a, unsigned long long b,
                                                    unsigned long long c) {
    unsigned long long d;
    asm("fma.rn.f32x2 %0, %1, %2, %3;" : "=l"(d) : "l"(a), "l"(b), "l"(c));
    return d;
}
__device__ __forceinline__ float hadd2(unsigned long long v) {
    float lo, hi;
    asm("mov.b64 {%0, %1}, %2;" : "=f"(lo), "=f"(hi) : "l"(v));
    return lo + hi;
}
__device__ __forceinline__ float2 unpk2(unsigned long long v) {
    float lo, hi;
    asm("mov.b64 {%0, %1}, %2;" : "=f"(lo), "=f"(hi) : "l"(v));
    return make_float2(lo, hi);
}

// ---------------- init: reset recurrent state every launch (determinism) ----------------
__global__ void init_state() {
    int i = blockIdx.x * blockDim.x + threadIdx.x;
    if (i < H * B) { g_h[i] = 0.f; g_c[i] = 0.f; g_attn[i] = 0.f; }
}

// ---------------- transpose x[B,T,Din] -> g_xT[t][k][b] ----------------
__global__ void transpose_x(const float* __restrict__ x) {
    __shared__ float sm[32][33];
    int t  = blockIdx.x;
    int k0 = blockIdx.y * 32;
    int tx = threadIdx.x, ty = threadIdx.y;   // (32, 8)
#pragma unroll
    for (int i = 0; i < 4; i++) {
        int b = ty + i * 8;
        sm[b][tx] = x[(b * T + t) * DIN + k0 + tx];   // coalesced over k
    }
    __syncthreads();
#pragma unroll
    for (int i = 0; i < 4; i++) {
        int k = ty + i * 8;
        g_xT[(t * DIN + k0 + k) * B + tx] = sm[tx][k]; // coalesced over b
    }
}

// ---------------- P = context @ Wq, tiled GEMM: M=B*S=4096, N=H, K=C ----------------
__global__ void __launch_bounds__(256) compute_P_tiled(const float* __restrict__ context,
                                                       const float* __restrict__ Wq) {
    __shared__ float sA[16][68];   // [k][m], padded
    __shared__ float sB[16][64];   // [k][n]
    int tid = threadIdx.x;
    int rm0 = blockIdx.x * 64;     // row tile (b*S+s)
    int cn0 = blockIdx.y * 64;     // h tile
    int ty = tid >> 4, tx = tid & 15;
    int m0 = ty * 4, n0 = tx * 4;

    unsigned long long acc[4][2];
#pragma unroll
    for (int i = 0; i < 4; i++) { acc[i][0] = 0ull; acc[i][1] = 0ull; }

    int lam = tid >> 2;            // 0..63 (m)
    int lak = (tid & 3) * 4;       // 0,4,8,12
    int lbk = tid >> 4;            // 0..15
    int lbn = (tid & 15) * 4;      // n

    for (int c0 = 0; c0 < C; c0 += 16) {
        float4 av = *(const float4*)(context + (rm0 + lam) * C + c0 + lak);
        sA[lak + 0][lam] = av.x; sA[lak + 1][lam] = av.y;
        sA[lak + 2][lam] = av.z; sA[lak + 3][lam] = av.w;
        *(float4*)(&sB[lbk][lbn]) = *(const float4*)(Wq + (c0 + lbk) * H + cn0 + lbn);
        __syncthreads();
#pragma unroll
        for (int k = 0; k < 16; k++) {
            float4 a4 = *(const float4*)(&sA[k][m0]);
            float4 b4 = *(const float4*)(&sB[k][n0]);
            unsigned long long b01 = pk2(b4.x, b4.y), b23 = pk2(b4.z, b4.w);
            float am[4] = {a4.x, a4.y, a4.z, a4.w};
#pragma unroll
            for (int i = 0; i < 4; i++) {
                unsigned long long a2 = pk2(am[i], am[i]);
                acc[i][0] = ffma2(a2, b01, acc[i][0]);
                acc[i][1] = ffma2(a2, b23, acc[i][1]);
            }
        }
        __syncthreads();
    }
#pragma unroll
    for (int i = 0; i < 4; i++) {
        float2 lo = unpk2(acc[i][0]), hi = unpk2(acc[i][1]);
        *(float4*)(g_P + (rm0 + m0 + i) * H + cn0 + n0) = make_float4(lo.x, lo.y, hi.x, hi.y);
    }
}

// ---------------- gates partial GEMMs: 12 chunks (3 segments x 4 K-chunks of 256) ----------
// 4 rows x 4 cols per thread, k-packed FFMA2. grid (32, 12) x 256 -> 98304 threads.
__global__ void __launch_bounds__(256) gates_part(const float* __restrict__ W_ih,
                                                  const float* __restrict__ W_hh, int t) {
    int segc  = blockIdx.y;                    // 0..11
    int seg   = segc >> 2;
    int k0    = (segc & 3) * 256;
    int gt    = blockIdx.x * 256 + threadIdx.x;  // 0..8191
    int r0    = (gt >> 3) * 4;                 // rows r0..r0+3
    int bq    = (gt & 7) * 4;                  // batch cols bq..bq+3

    const float* w;
    const float* act;
    int ws;
    if (seg == 0)      { w = W_ih + r0 * 2048 + k0;        act = g_xT + t * DIN * B + k0 * B; ws = 2048; }
    else if (seg == 1) { w = W_ih + r0 * 2048 + 1024 + k0; act = g_attn + k0 * B;             ws = 2048; }
    else               { w = W_hh + r0 * 1024 + k0;        act = g_h + k0 * B;                ws = 1024; }

    unsigned long long acc[4][4];
#pragma unroll
    for (int i = 0; i < 4; i++)
#pragma unroll
        for (int c = 0; c < 4; c++) acc[i][c] = 0ull;

#pragma unroll 2
    for (int k = 0; k < 256; k += 4) {
        float4 wv0 = *(const float4*)(w + k);
        float4 wv1 = *(const float4*)(w + ws + k);
        float4 wv2 = *(const float4*)(w + 2 * ws + k);
        float4 wv3 = *(const float4*)(w + 3 * ws + k);
        float4 a0 = *(const float4*)(act + (k + 0) * B + bq);
        float4 a1 = *(const float4*)(act + (k + 1) * B + bq);
        float4 a2 = *(const float4*)(act + (k + 2) * B + bq);
        float4 a3 = *(const float4*)(act + (k + 3) * B + bq);
        {   // k-pair (k, k+1)
            unsigned long long px = pk2(a0.x, a1.x), py = pk2(a0.y, a1.y);
            unsigned long long pz = pk2(a0.z, a1.z), pw = pk2(a0.w, a1.w);
            unsigned long long q0 = pk2(wv0.x, wv0.y), q1 = pk2(wv1.x, wv1.y);
            unsigned long long q2 = pk2(wv2.x, wv2.y), q3 = pk2(wv3.x, wv3.y);
            acc[0][0] = ffma2(q0, px, acc[0][0]); acc[0][1] = ffma2(q0, py, acc[0][1]);
            acc[0][2] = ffma2(q0, pz, acc[0][2]); acc[0][3] = ffma2(q0, pw, acc[0][3]);
            acc[1][0] = ffma2(q1, px, acc[1][0]); acc[1][1] = ffma2(q1, py, acc[1][1]);
            acc[1][2] = ffma2(q1, pz, acc[1][2]); acc[1][3] = ffma2(q1, pw, acc[1][3]);
            acc[2][0] = ffma2(q2, px, acc[2][0]); acc[2][1] = ffma2(q2, py, acc[2][1]);
            acc[2][2] = ffma2(q2, pz, acc[2][2]); acc[2][3] = ffma2(q2, pw, acc[2][3]);
            acc[3][0] = ffma2(q3, px, acc[3][0]); acc[3][1] = ffma2(q3, py, acc[3][1]);
            acc[3][2] = ffma2(q3, pz, acc[3][2]); acc[3][3] = ffma2(q3, pw, acc[3][3]);
        }
        {   // k-pair (k+2, k+3)
            unsigned long long px = pk2(a2.x, a3.x), py = pk2(a2.y, a3.y);
            unsigned long long pz = pk2(a2.z, a3.z), pw = pk2(a2.w, a3.w);
            unsigned long long q0 = pk2(wv0.z, wv0.w), q1 = pk2(wv1.z, wv1.w);
            unsigned long long q2 = pk2(wv2.z, wv2.w), q3 = pk2(wv3.z, wv3.w);
            acc[0][0] = ffma2(q0, px, acc[0][0]); acc[0][1] = ffma2(q0, py, acc[0][1]);
            acc[0][2] = ffma2(q0, pz, acc[0][2]); acc[0][3] = ffma2(q0, pw, acc[0][3]);
            acc[1][0] = ffma2(q1, px, acc[1][0]); acc[1][1] = ffma2(q1, py, acc[1][1]);
            acc[1][2] = ffma2(q1, pz, acc[1][2]); acc[1][3] = ffma2(q1, pw, acc[1][3]);
            acc[2][0] = ffma2(q2, px, acc[2][0]); acc[2][1] = ffma2(q2, py, acc[2][1]);
            acc[2][2] = ffma2(q2, pz, acc[2][2]); acc[2][3] = ffma2(q2, pw, acc[2][3]);
            acc[3][0] = ffma2(q3, px, acc[3][0]); acc[3][1] = ffma2(q3, py, acc[3][1]);
            acc[3][2] = ffma2(q3, pz, acc[3][2]); acc[3][3] = ffma2(q3, pw, acc[3][3]);
        }
    }

#pragma unroll
    for (int i = 0; i < 4; i++) {
        float4 o = make_float4(hadd2(acc[i][0]), hadd2(acc[i][1]),
                               hadd2(acc[i][2]), hadd2(acc[i][3]));
        *(float4*)(&g_gp[segc][(r0 + i) * B + bq]) = o;
    }
}

// ---------------- cell + partial scores: grid (B, 4), 256 threads ----------------
// Block (b,q) owns features [q*256, q*256+256): sums 12 gate partials + biases,
// computes the cell update, keeps h-slice in smem, then emits partial scores
// sp[b][s][q] = sum_{j in slice} h_j * P[b,s,j] for all s.
__global__ void __launch_bounds__(256) cell_scores(const float* __restrict__ b_ih,
                                                   const float* __restrict__ b_hh) {
    __shared__ float sh[256];
    int b   = blockIdx.x;
    int q   = blockIdx.y;
    int tid = threadIdx.x;
    int j   = q * 256 + tid;

    // ---- cell update for feature j, batch b ----
    {
        float gs[4];
#pragma unroll
        for (int g = 0; g < 4; g++) {
            int idx = (g * H + j) * B + b;
            float v = b_ih[g * H + j] + b_hh[g * H + j];
#pragma unroll
            for (int p = 0; p < NGP; p++) v += g_gp[p][idx];
            gs[g] = v;
        }
        float c  = g_c[j * B + b];
        float cn = sigf(gs[1]) * c + sigf(gs[0]) * tanhf(gs[2]);
        float hn = sigf(gs[3]) * tanhf(cn);
        g_c[j * B + b] = cn;
        g_h[j * B + b] = hn;
        sh[tid] = hn;
    }
    __syncthreads();

    // ---- partial scores: each warp handles 16 of the S=128 scores ----
    int wrp  = tid >> 5;
    int lane = tid & 31;
    float4 h0 = *(const float4*)(sh + lane * 8);
    float4 h1 = *(const float4*)(sh + lane * 8 + 4);

    for (int s = wrp; s < S; s += 8) {
        const float* p = g_P + (b * S + s) * H + q * 256 + lane * 8;
        float4 p0 = *(const float4*)(p);
        float4 p1 = *(const float4*)(p + 4);
        float acc = p0.x * h0.x + p0.y * h0.y + p0.z * h0.z + p0.w * h0.w
                  + p1.x * h1.x + p1.y * h1.y + p1.z * h1.z + p1.w * h1.w;
#pragma unroll
        for (int o = 16; o > 0; o >>= 1) acc += __shfl_xor_sync(0xffffffffu, acc, o);
        if (lane == 0) ((float*)&g_sp4[b * S + s])[q] = acc;
    }
}

// ---------------- softmax + ctx: grid (B, 4), 256 threads ----------------
__global__ void __launch_bounds__(256) softmax_ctx2(const float* __restrict__ context) {
    __shared__ float sal[128];
    __shared__ float sred[128];
    int b   = blockIdx.x;
    int cq  = blockIdx.y;
    int tid = threadIdx.x;

    float sc = 0.f;
    if (tid < 128) {
        float4 sp = g_sp4[b * S + tid];
        sc = (sp.x + sp.y) + (sp.z + sp.w);
        sred[tid] = sc;
    }
    __syncthreads();
#pragma unroll
    for (int o = 64; o > 0; o >>= 1) {
        if (tid < o) sred[tid] = fmaxf(sred[tid], sred[tid + o]);
        __syncthreads();
    }
    float mx = sred[0];
    __syncthreads();
    float e = 0.f;
    if (tid < 128) { e = expf(sc - mx); sred[tid] = e; }
    __syncthreads();
#pragma unroll
    for (int o = 64; o > 0; o >>= 1) {
        if (tid < o) sred[tid] += sred[tid + o];
        __syncthreads();
    }
    float inv = 1.f / sred[0];
    __syncthreads();
    if (tid < 128) sal[tid] = e * inv;   // normalized alpha
    __syncthreads();

    // ---- ctx: one channel per thread ----
    int c = cq * 256 + tid;
    const float* cb = context + b * S * C + c;
    float acc = 0.f;
#pragma unroll 8
    for (int s = 0; s < S; s++) acc += sal[s] * cb[s * C];
    g_ctx[c * B + b] = acc;
}

// ---------------- output projection partials: 8 K-chunks of 256, 2 rows x 4 cols ---------
// chunks 0-3: Wout cols [c*256, ..] @ ctx slice;  chunks 4-7: @ h slice.
// grid (16, 8) x 256 -> 32768 threads.
__global__ void __launch_bounds__(256) out_part(const float* __restrict__ Wout) {
    int segc = blockIdx.y;                       // 0..7
    int gt   = blockIdx.x * 256 + threadIdx.x;   // 0..4095
    int r0   = (gt >> 3) * 2;                    // rows r0, r0+1
    int bq   = (gt & 7) * 4;
    const float* w   = Wout + r0 * 2048 + segc * 256;
    const float* act = (segc < 4 ? g_ctx : g_h) + (segc & 3) * 256 * B;

    unsigned long long acc[2][4];
#pragma unroll
    for (int i = 0; i < 2; i++)
#pragma unroll
        for (int c = 0; c < 4; c++) acc[i][c] = 0ull;

#pragma unroll 2
    for (int k = 0; k < 256; k += 4) {
        float4 wv0 = *(const float4*)(w + k);
        float4 wv1 = *(const float4*)(w + 2048 + k);
        float4 a0 = *(const float4*)(act + (k + 0) * B + bq);
        float4 a1 = *(const float4*)(act + (k + 1) * B + bq);
        float4 a2 = *(const float4*)(act + (k + 2) * B + bq);
        float4 a3 = *(const float4*)(act + (k + 3) * B + bq);
        {
            unsigned long long px = pk2(a0.x, a1.x), py = pk2(a0.y, a1.y);
            unsigned long long pz = pk2(a0.z, a1.z), pw = pk2(a0.w, a1.w);
            unsigned long long q0 = pk2(wv0.x, wv0.y), q1 = pk2(wv1.x, wv1.y);
            acc[0][0] = ffma2(q0, px, acc[0][0]); acc[0][1] = ffma2(q0, py, acc[0][1]);
            acc[0][2] = ffma2(q0, pz, acc[0][2]); acc[0][3] = ffma2(q0, pw, acc[0][3]);
            acc[1][0] = ffma2(q1, px, acc[1][0]); acc[1][1] = ffma2(q1, py, acc[1][1]);
            acc[1][2] = ffma2(q1, pz, acc[1][2]); acc[1][3] = ffma2(q1, pw, acc[1][3]);
        }
        {
            unsigned long long px = pk2(a2.x, a3.x), py = pk2(a2.y, a3.y);
            unsigned long long pz = pk2(a2.z, a3.z), pw = pk2(a2.w, a3.w);
            unsigned long long q0 = pk2(wv0.z, wv0.w), q1 = pk2(wv1.z, wv1.w);
            acc[0][0] = ffma2(q0, px, acc[0][0]); acc[0][1] = ffma2(q0, py, acc[0][1]);
            acc[0][2] = ffma2(q0, pz, acc[0][2]); acc[0][3] = ffma2(q0, pw, acc[0][3]);
            acc[1][0] = ffma2(q1, px, acc[1][0]); acc[1][1] = ffma2(q1, py, acc[1][1]);
            acc[1][2] = ffma2(q1, pz, acc[1][2]); acc[1][3] = ffma2(q1, pw, acc[1][3]);
        }
    }

#pragma unroll
    for (int i = 0; i < 2; i++) {
        float4 o = make_float4(hadd2(acc[i][0]), hadd2(acc[i][1]),
                               hadd2(acc[i][2]), hadd2(acc[i][3]));
        *(float4*)(&g_op[segc][(r0 + i) * B + bq]) = o;
    }
}

// ---------------- combine output partials, tanh, write attn state + final output ----------
__global__ void __launch_bounds__(256) out_combine(const float* __restrict__ b_out,
                                                   float* __restrict__ out, int t) {
    int tid = blockIdx.x * blockDim.x + threadIdx.x;   // 32768
    int b = tid & 31, r = tid >> 5;
    int idx = r * B + b;
    float v = b_out[r];
#pragma unroll
    for (int p = 0; p < NOP; p++) v += g_op[p][idx];
    v = tanhf(v);
    g_attn[idx] = v;
    out[b * (T * H) + t * H + r] = v;
}

// ---------------- launch ----------------
extern "C" void kernel_launch(void* const* d_in, const int* in_sizes, int n_in,
                              void* d_out, int out_size) {
    const float* x       = (const float*)d_in[0];
    const float* context = (const float*)d_in[1];
    const float* W_ih    = (const float*)d_in[2];
    const float* W_hh    = (const float*)d_in[3];
    const float* b_ih    = (const float*)d_in[4];
    const float* b_hh    = (const float*)d_in[5];
    const float* Wq      = (const float*)d_in[6];
    const float* Wout    = (const float*)d_in[7];
    const float* b_out   = (const float*)d_in[8];
    float* out = (float*)d_out;

    init_state<<<(H * B) / 256, 256>>>();
    transpose_x<<<dim3(T, DIN / 32), dim3(32, 8)>>>(x);
    compute_P_tiled<<<dim3(64, 16), 256>>>(context, Wq);

    for (int t = 0; t < T; t++) {
        gates_part<<<dim3(32, 12), 256>>>(W_ih, W_hh, t);
        cell_scores<<<dim3(B, 4), 256>>>(b_ih, b_hh);
        softmax_ctx2<<<dim3(B, 4), 256>>>(context);
        out_part<<<dim3(16, 8), 256>>>(Wout);
        out_combine<<<128, 256>>>(b_out, out, t);
    }
}